// round 9
// baseline (speedup 1.0000x reference)
#include <cuda_runtime.h>
#include <cuda_bf16.h>

#define NN 50000
#define NE 800000
#define SCAN_BLOCKS 49   // ceil(50000/1024)

// ---- scratch (__device__ globals; no allocation allowed) -------------------
__device__ float4 g_y[NN * 32];    // {ys, yv0, yv1, yv2} post-lin1
__device__ float  g_h[NE * 8];     // silu(eb @ fc_w1 / sqrt8) per edge
__device__ int    g_count[NN];     // dst degree histogram
__device__ int    g_start[NN];     // CSR offsets (exclusive scan of count)
__device__ int    g_cursor[NN];    // scatter cursors
__device__ int    g_bsum[SCAN_BLOCKS];
__device__ int2   g_se[NE];        // dst-sorted {src, edge_id}

// ---------------------------------------------------------------------------
// Kernel 1: per-node prep. ys/yv = lin1(x); self-connection -> out.
// Also zeroes g_count[n] (histogram runs in the next kernel).
// Warp per node, lane = output channel w.
// ---------------------------------------------------------------------------
__global__ void node_prep_kernel(const float* __restrict__ nf,
                                 const float* __restrict__ nattr,
                                 const float* __restrict__ W1s,
                                 const float* __restrict__ W1v,
                                 const float* __restrict__ Wscs,
                                 const float* __restrict__ Wscv,
                                 float* __restrict__ out) {
    __shared__ float2 sW1[1024];   // [u][w] -> {W1s, W1v}
    __shared__ float2 sWsc[4096];  // [u][sp][w] -> {Wscs, Wscv}
    __shared__ float4 sRow[8][32]; // packed {xs, xv0, xv1, xv2} per u

    const int tid = threadIdx.x;
    for (int i = tid; i < 1024; i += 256) sW1[i] = make_float2(W1s[i], W1v[i]);
    for (int i = tid; i < 4096; i += 256) sWsc[i] = make_float2(Wscs[i], Wscv[i]);
    __syncthreads();

    const int warp = tid >> 5, lane = tid & 31;
    const int nwarps = gridDim.x * 8;
    const float l1n = 0.17677669529663687f;  // 1/sqrt(32)
    const float scn = 0.08838834764831843f;  // 1/sqrt(32*4)

    for (int n = blockIdx.x * 8 + warp; n < NN; n += nwarps) {
        const float* row = nf + (size_t)n * 128;
        {
            float xs = __ldg(row + lane);
            float x0 = __ldg(row + 32 + lane * 3 + 0);
            float x1 = __ldg(row + 32 + lane * 3 + 1);
            float x2 = __ldg(row + 32 + lane * 3 + 2);
            sRow[warp][lane] = make_float4(xs, x0, x1, x2);
        }
        if (lane == 0) g_count[n] = 0;
        __syncwarp();

        int sp = 0;
#pragma unroll
        for (int v = 0; v < 4; v++)
            if (nattr[n * 4 + v] > 0.5f) sp = v;

        const int w = lane;
        float ys = 0.f, yv0 = 0.f, yv1 = 0.f, yv2 = 0.f;
        float ss = 0.f, sv0 = 0.f, sv1 = 0.f, sv2 = 0.f;
        const float2* wsc = sWsc + sp * 32 + w;
#pragma unroll 8
        for (int u = 0; u < 32; u++) {
            float4 x = sRow[warp][u];            // 1 LDS.128 broadcast
            float2 ab = sW1[u * 32 + w];
            ys  = fmaf(x.x, ab.x, ys);
            yv0 = fmaf(x.y, ab.y, yv0);
            yv1 = fmaf(x.z, ab.y, yv1);
            yv2 = fmaf(x.w, ab.y, yv2);
            float2 cd = wsc[u * 128];
            ss  = fmaf(x.x, cd.x, ss);
            sv0 = fmaf(x.y, cd.y, sv0);
            sv1 = fmaf(x.z, cd.y, sv1);
            sv2 = fmaf(x.w, cd.y, sv2);
        }

        g_y[n * 32 + w] = make_float4(ys * l1n, yv0 * l1n, yv1 * l1n, yv2 * l1n);

        float* orow = out + (size_t)n * 128;
        orow[w] = ss * scn;
        orow[32 + w * 3 + 0] = sv0 * scn;
        orow[32 + w * 3 + 1] = sv1 * scn;
        orow[32 + w * 3 + 2] = sv2 * scn;
        __syncwarp();
    }
}

// ---------------------------------------------------------------------------
// Kernel 2: h-pass + histogram. 8 lanes per edge (4 edges per warp).
// Lane (g,j) computes h[e_g][j] = silu((eb[e_g] @ fc_w1[:,j]) / sqrt8).
// Full MUFU efficiency (all 32 lanes useful). Also histograms dst.
// NE is divisible by 4, so warp tasks are all-or-nothing valid.
// ---------------------------------------------------------------------------
__global__ void h_pass_kernel(const float* __restrict__ eb,
                              const int* __restrict__ ei,
                              const float* __restrict__ fw1) {
    const int tid = threadIdx.x;
    const int lane = tid & 31;
    const int g = lane >> 3, j = lane & 7;
    const int gwarp = (blockIdx.x * blockDim.x + tid) >> 5;
    const int nwarps = (gridDim.x * blockDim.x) >> 5;
    const float is8 = 0.3535533905932738f;

    float w1c[8];
#pragma unroll
    for (int k = 0; k < 8; k++) w1c[k] = __ldg(fw1 + k * 8 + j);

    const int ntasks = NE / 4;
    for (int t = gwarp; t < ntasks; t += nwarps) {
        const int e = t * 4 + g;
        float myeb = __ldg(eb + (size_t)e * 8 + j);

        float acc = 0.f;
#pragma unroll
        for (int k = 0; k < 8; k++)
            acc = fmaf(__shfl_sync(0xffffffffu, myeb, (g << 3) + k), w1c[k], acc);
        acc *= is8;
        float hv = __fdividef(acc, 1.f + __expf(-acc));  // silu

        g_h[(size_t)e * 8 + j] = hv;   // fully coalesced across warp

        if (j == 0) atomicAdd(&g_count[__ldg(ei + NE + e)], 1);
    }
}

// ---------------------------------------------------------------------------
// Kernels 3a/3b/3c: exclusive prefix scan of g_count -> g_start, g_cursor.
// ---------------------------------------------------------------------------
__global__ void scan1_kernel() {
    __shared__ int sh[1024];
    const int i = blockIdx.x * 1024 + threadIdx.x;
    const int v = (i < NN) ? g_count[i] : 0;
    sh[threadIdx.x] = v;
    __syncthreads();
#pragma unroll
    for (int off = 1; off < 1024; off <<= 1) {
        int t = (threadIdx.x >= off) ? sh[threadIdx.x - off] : 0;
        __syncthreads();
        sh[threadIdx.x] += t;
        __syncthreads();
    }
    if (i < NN) g_start[i] = sh[threadIdx.x] - v;  // exclusive
    if (threadIdx.x == 1023) g_bsum[blockIdx.x] = sh[1023];
}

__global__ void scan2_kernel() {
    __shared__ int sh[64];
    const int t = threadIdx.x;
    const int v = (t < SCAN_BLOCKS) ? g_bsum[t] : 0;
    sh[t] = v;
    __syncthreads();
#pragma unroll
    for (int off = 1; off < 64; off <<= 1) {
        int x = (t >= off) ? sh[t - off] : 0;
        __syncthreads();
        sh[t] += x;
        __syncthreads();
    }
    if (t < SCAN_BLOCKS) g_bsum[t] = sh[t] - v;   // exclusive block offsets
}

__global__ void scan3_kernel() {
    const int i = blockIdx.x * 1024 + threadIdx.x;
    if (i < NN) {
        int s = g_start[i] + g_bsum[blockIdx.x];
        g_start[i] = s;
        g_cursor[i] = s;
    }
}

// ---------------------------------------------------------------------------
// Kernel 4: scatter edges into dst-sorted order.
// ---------------------------------------------------------------------------
__global__ void scatter_kernel(const int* __restrict__ ei) {
    const int stride = gridDim.x * blockDim.x;
    for (int e = blockIdx.x * blockDim.x + threadIdx.x; e < NE; e += stride) {
        int src = __ldg(ei + e);
        int dst = __ldg(ei + NE + e);
        int pos = atomicAdd(&g_cursor[dst], 1);
        g_se[pos] = make_int2(src, e);
    }
}

// ---------------------------------------------------------------------------
// Kernel 5: fused dst-accumulate + lin2. Warp per dst node, lane = channel u.
// Atomic-free: A/B accumulated in 8 registers over the node's CSR segment,
// then lin2 applied via shared staging; result added to out (sc already there).
// MLP layer-2 weights live in 32 registers (is8 pre-folded).
// ---------------------------------------------------------------------------
__global__ void __launch_bounds__(256) dst_fused_kernel(
                              const float* __restrict__ ea,
                              const float* __restrict__ fw2,
                              const float* __restrict__ W2s,
                              const float* __restrict__ W2v,
                              float* __restrict__ out) {
    __shared__ float2 sW2[2048];   // [u][w] -> {W2s, W2v}, u in [0,64)
    __shared__ float4 sMid[8][64];

    const int tid = threadIdx.x;
    for (int i = tid; i < 2048; i += 256) sW2[i] = make_float2(W2s[i], W2v[i]);
    __syncthreads();

    const int warp = tid >> 5, lane = tid & 31;
    const int nwarps = gridDim.x * 8;
    const int u = lane;
    const float is8 = 0.3535533905932738f;
    const float IS3 = 0.5773502691896258f;
    const float cc  = 0.25f * 0.125f;        // 1/sqrt(16) * 1/sqrt(64)

    float w2r[32];                            // [j][c], c = {w00,w01,w10,w11}
#pragma unroll
    for (int j = 0; j < 8; j++)
#pragma unroll
        for (int c = 0; c < 4; c++)
            w2r[j * 4 + c] = __ldg(fw2 + j * 128 + c * 32 + u) * is8;

    for (int n = blockIdx.x * 8 + warp; n < NN; n += nwarps) {
        const int start = g_start[n];
        const int cnt   = g_count[n];

        float As = 0.f, Av0 = 0.f, Av1 = 0.f, Av2 = 0.f;
        float Bs = 0.f, Bv0 = 0.f, Bv1 = 0.f, Bv2 = 0.f;

        int2 se = (cnt > 0) ? __ldg(&g_se[start]) : make_int2(0, 0);
        for (int t = 0; t < cnt; t++) {
            const int src = se.x;
            const int e   = se.y;
            // prefetch next edge's {src,eid} to break the serial load chain
            if (t + 1 < cnt) se = __ldg(&g_se[start + t + 1]);

            const float4 y  = __ldg(&g_y[src * 32 + u]);                    // coalesced
            const float4 av = __ldg((const float4*)(ea + (size_t)e * 4));   // broadcast
            const float4 h0 = __ldg((const float4*)(g_h + (size_t)e * 8));
            const float4 h1 = __ldg((const float4*)(g_h + (size_t)e * 8 + 4));

            // MLP layer 2 (register-resident weights)
            float w00, w01, w10, w11;
            w00 = h0.x * w2r[0];
            w01 = h0.x * w2r[1];
            w10 = h0.x * w2r[2];
            w11 = h0.x * w2r[3];
            w00 = fmaf(h0.y, w2r[4],  w00); w01 = fmaf(h0.y, w2r[5],  w01);
            w10 = fmaf(h0.y, w2r[6],  w10); w11 = fmaf(h0.y, w2r[7],  w11);
            w00 = fmaf(h0.z, w2r[8],  w00); w01 = fmaf(h0.z, w2r[9],  w01);
            w10 = fmaf(h0.z, w2r[10], w10); w11 = fmaf(h0.z, w2r[11], w11);
            w00 = fmaf(h0.w, w2r[12], w00); w01 = fmaf(h0.w, w2r[13], w01);
            w10 = fmaf(h0.w, w2r[14], w10); w11 = fmaf(h0.w, w2r[15], w11);
            w00 = fmaf(h1.x, w2r[16], w00); w01 = fmaf(h1.x, w2r[17], w01);
            w10 = fmaf(h1.x, w2r[18], w10); w11 = fmaf(h1.x, w2r[19], w11);
            w00 = fmaf(h1.y, w2r[20], w00); w01 = fmaf(h1.y, w2r[21], w01);
            w10 = fmaf(h1.y, w2r[22], w10); w11 = fmaf(h1.y, w2r[23], w11);
            w00 = fmaf(h1.z, w2r[24], w00); w01 = fmaf(h1.z, w2r[25], w01);
            w10 = fmaf(h1.z, w2r[26], w10); w11 = fmaf(h1.z, w2r[27], w11);
            w00 = fmaf(h1.w, w2r[28], w00); w01 = fmaf(h1.w, w2r[29], w01);
            w10 = fmaf(h1.w, w2r[30], w10); w11 = fmaf(h1.w, w2r[31], w11);

            const float es    = y.x;
            const float dotv  = fmaf(y.y, av.y, fmaf(y.z, av.z, y.w * av.w));
            const float wes   = w01 * es;
            const float w10a0 = w10 * av.x;

            As  += w00 * es * av.x;
            Bs  += w11 * dotv * IS3;
            Av0 = fmaf(wes, av.y, Av0);
            Av1 = fmaf(wes, av.z, Av1);
            Av2 = fmaf(wes, av.w, Av2);
            Bv0 = fmaf(w10a0, y.y, Bv0);
            Bv1 = fmaf(w10a0, y.z, Bv1);
            Bv2 = fmaf(w10a0, y.w, Bv2);
        }

        // stage mid into shared, then lin2 (cross-channel mix)
        sMid[warp][u]      = make_float4(As, Av0, Av1, Av2);
        sMid[warp][32 + u] = make_float4(Bs, Bv0, Bv1, Bv2);
        __syncwarp();

        const int w = lane;
        float os = 0.f, ov0 = 0.f, ov1 = 0.f, ov2 = 0.f;
#pragma unroll 16
        for (int uu = 0; uu < 64; uu++) {
            float4 m  = sMid[warp][uu];
            float2 ab = sW2[uu * 32 + w];
            os  = fmaf(m.x, ab.x, os);
            ov0 = fmaf(m.y, ab.y, ov0);
            ov1 = fmaf(m.z, ab.y, ov1);
            ov2 = fmaf(m.w, ab.y, ov2);
        }

        float* orow = out + (size_t)n * 128;
        orow[w]              += os  * cc;
        orow[32 + w * 3 + 0] += ov0 * cc;
        orow[32 + w * 3 + 1] += ov1 * cc;
        orow[32 + w * 3 + 2] += ov2 * cc;
        __syncwarp();
    }
}

// ---------------------------------------------------------------------------
extern "C" void kernel_launch(void* const* d_in, const int* in_sizes, int n_in,
                              void* d_out, int out_size) {
    const float* nf    = (const float*)d_in[0];   // node_features (N, 128)
    const float* nattr = (const float*)d_in[1];   // node_attr (N, 4)
    const float* eb    = (const float*)d_in[2];   // edge_embedding (E, 8)
    const float* ea    = (const float*)d_in[3];   // edge_attr (E, 4)
    const int*   ei    = (const int*)d_in[4];     // edge_index (2, E)
    const float* W1s   = (const float*)d_in[5];
    const float* W1v   = (const float*)d_in[6];
    const float* fw1   = (const float*)d_in[7];
    const float* fw2   = (const float*)d_in[8];
    const float* W2s   = (const float*)d_in[9];
    const float* W2v   = (const float*)d_in[10];
    const float* Wscs  = (const float*)d_in[11];
    const float* Wscv  = (const float*)d_in[12];
    float* out = (float*)d_out;

    node_prep_kernel<<<1184, 256>>>(nf, nattr, W1s, W1v, Wscs, Wscv, out);
    h_pass_kernel<<<1184, 256>>>(eb, ei, fw1);
    scan1_kernel<<<SCAN_BLOCKS, 1024>>>();
    scan2_kernel<<<1, 64>>>();
    scan3_kernel<<<SCAN_BLOCKS, 1024>>>();
    scatter_kernel<<<1184, 256>>>(ei);
    dst_fused_kernel<<<1184, 256>>>(ea, fw2, W2s, W2v, out);
}

// round 10
// speedup vs baseline: 1.0551x; 1.0551x over previous
#include <cuda_runtime.h>
#include <cuda_bf16.h>

#define NN 50000
#define NE 800000
#define SCAN_BLOCKS 49   // ceil(50000/1024)

// ---- scratch (__device__ globals; no allocation allowed) -------------------
__device__ float4 g_y[NN * 32];    // {ys, yv0, yv1, yv2} post-lin1
__device__ float  g_h[NE * 8];     // silu(eb @ fc_w1 / sqrt8) per edge
__device__ int    g_count[NN];     // dst degree histogram
__device__ int    g_start[NN];     // CSR offsets (exclusive scan of count)
__device__ int    g_cursor[NN];    // scatter cursors
__device__ int    g_bsum[SCAN_BLOCKS];
__device__ int2   g_se[NE];        // dst-sorted {src, edge_id}

// ---------------------------------------------------------------------------
// Kernel 1: per-node prep. ys/yv = lin1(x); self-connection -> out.
// Node row loaded with ONE coalesced LDG.128 per lane (512B/warp exact,
// no stride-3 over-fetch), repacked via smem. Also zeroes g_count.
// Warp per node, lane = output channel w.
// ---------------------------------------------------------------------------
__global__ void node_prep_kernel(const float* __restrict__ nf,
                                 const float* __restrict__ nattr,
                                 const float* __restrict__ W1s,
                                 const float* __restrict__ W1v,
                                 const float* __restrict__ Wscs,
                                 const float* __restrict__ Wscv,
                                 float* __restrict__ out) {
    __shared__ float2 sW1[1024];    // [u][w] -> {W1s, W1v}
    __shared__ float2 sWsc[4096];   // [u][sp][w] -> {Wscs, Wscv}
    __shared__ float4 sRaw4[8][32]; // raw row, coalesced
    __shared__ float4 sRow[8][32];  // packed {xs, xv0, xv1, xv2} per u

    const int tid = threadIdx.x;
    for (int i = tid; i < 1024; i += 256) sW1[i] = make_float2(W1s[i], W1v[i]);
    for (int i = tid; i < 4096; i += 256) sWsc[i] = make_float2(Wscs[i], Wscv[i]);
    __syncthreads();

    const int warp = tid >> 5, lane = tid & 31;
    const int nwarps = gridDim.x * 8;
    const float l1n = 0.17677669529663687f;  // 1/sqrt(32)
    const float scn = 0.08838834764831843f;  // 1/sqrt(32*4)

    for (int n = blockIdx.x * 8 + warp; n < NN; n += nwarps) {
        // coalesced row load: 32 lanes x float4 = 512B = whole row
        sRaw4[warp][lane] = __ldg((const float4*)(nf + (size_t)n * 128) + lane);
        if (lane == 0) g_count[n] = 0;
        __syncwarp();
        {
            const float* raw = (const float*)sRaw4[warp];
            float xs = raw[lane];
            float x0 = raw[32 + lane * 3 + 0];
            float x1 = raw[32 + lane * 3 + 1];
            float x2 = raw[32 + lane * 3 + 2];
            sRow[warp][lane] = make_float4(xs, x0, x1, x2);
        }
        __syncwarp();

        int sp = 0;
#pragma unroll
        for (int v = 0; v < 4; v++)
            if (nattr[n * 4 + v] > 0.5f) sp = v;

        const int w = lane;
        float ys = 0.f, yv0 = 0.f, yv1 = 0.f, yv2 = 0.f;
        float ss = 0.f, sv0 = 0.f, sv1 = 0.f, sv2 = 0.f;
        const float2* wsc = sWsc + sp * 32 + w;
#pragma unroll 8
        for (int u = 0; u < 32; u++) {
            float4 x = sRow[warp][u];            // 1 LDS.128 broadcast
            float2 ab = sW1[u * 32 + w];
            ys  = fmaf(x.x, ab.x, ys);
            yv0 = fmaf(x.y, ab.y, yv0);
            yv1 = fmaf(x.z, ab.y, yv1);
            yv2 = fmaf(x.w, ab.y, yv2);
            float2 cd = wsc[u * 128];
            ss  = fmaf(x.x, cd.x, ss);
            sv0 = fmaf(x.y, cd.y, sv0);
            sv1 = fmaf(x.z, cd.y, sv1);
            sv2 = fmaf(x.w, cd.y, sv2);
        }

        g_y[n * 32 + w] = make_float4(ys * l1n, yv0 * l1n, yv1 * l1n, yv2 * l1n);

        float* orow = out + (size_t)n * 128;
        orow[w] = ss * scn;
        orow[32 + w * 3 + 0] = sv0 * scn;
        orow[32 + w * 3 + 1] = sv1 * scn;
        orow[32 + w * 3 + 2] = sv2 * scn;
        __syncwarp();
    }
}

// ---------------------------------------------------------------------------
// Kernel 2: h-pass + histogram. 8 lanes per edge (4 edges per warp).
// ---------------------------------------------------------------------------
__global__ void h_pass_kernel(const float* __restrict__ eb,
                              const int* __restrict__ ei,
                              const float* __restrict__ fw1) {
    const int tid = threadIdx.x;
    const int lane = tid & 31;
    const int g = lane >> 3, j = lane & 7;
    const int gwarp = (blockIdx.x * blockDim.x + tid) >> 5;
    const int nwarps = (gridDim.x * blockDim.x) >> 5;
    const float is8 = 0.3535533905932738f;

    float w1c[8];
#pragma unroll
    for (int k = 0; k < 8; k++) w1c[k] = __ldg(fw1 + k * 8 + j);

    const int ntasks = NE / 4;
    for (int t = gwarp; t < ntasks; t += nwarps) {
        const int e = t * 4 + g;
        float myeb = __ldg(eb + (size_t)e * 8 + j);

        float acc = 0.f;
#pragma unroll
        for (int k = 0; k < 8; k++)
            acc = fmaf(__shfl_sync(0xffffffffu, myeb, (g << 3) + k), w1c[k], acc);
        acc *= is8;
        float hv = __fdividef(acc, 1.f + __expf(-acc));  // silu

        g_h[(size_t)e * 8 + j] = hv;   // fully coalesced across warp

        if (j == 0) atomicAdd(&g_count[__ldg(ei + NE + e)], 1);
    }
}

// ---------------------------------------------------------------------------
// Kernels 3a/3b/3c: exclusive prefix scan of g_count -> g_start, g_cursor.
// ---------------------------------------------------------------------------
__global__ void scan1_kernel() {
    __shared__ int sh[1024];
    const int i = blockIdx.x * 1024 + threadIdx.x;
    const int v = (i < NN) ? g_count[i] : 0;
    sh[threadIdx.x] = v;
    __syncthreads();
#pragma unroll
    for (int off = 1; off < 1024; off <<= 1) {
        int t = (threadIdx.x >= off) ? sh[threadIdx.x - off] : 0;
        __syncthreads();
        sh[threadIdx.x] += t;
        __syncthreads();
    }
    if (i < NN) g_start[i] = sh[threadIdx.x] - v;  // exclusive
    if (threadIdx.x == 1023) g_bsum[blockIdx.x] = sh[1023];
}

__global__ void scan2_kernel() {
    __shared__ int sh[64];
    const int t = threadIdx.x;
    const int v = (t < SCAN_BLOCKS) ? g_bsum[t] : 0;
    sh[t] = v;
    __syncthreads();
#pragma unroll
    for (int off = 1; off < 64; off <<= 1) {
        int x = (t >= off) ? sh[t - off] : 0;
        __syncthreads();
        sh[t] += x;
        __syncthreads();
    }
    if (t < SCAN_BLOCKS) g_bsum[t] = sh[t] - v;   // exclusive block offsets
}

__global__ void scan3_kernel() {
    const int i = blockIdx.x * 1024 + threadIdx.x;
    if (i < NN) {
        int s = g_start[i] + g_bsum[blockIdx.x];
        g_start[i] = s;
        g_cursor[i] = s;
    }
}

// ---------------------------------------------------------------------------
// Kernel 4: scatter edges into dst-sorted order.
// ---------------------------------------------------------------------------
__global__ void scatter_kernel(const int* __restrict__ ei) {
    const int stride = gridDim.x * blockDim.x;
    for (int e = blockIdx.x * blockDim.x + threadIdx.x; e < NE; e += stride) {
        int src = __ldg(ei + e);
        int dst = __ldg(ei + NE + e);
        int pos = atomicAdd(&g_cursor[dst], 1);
        g_se[pos] = make_int2(src, e);
    }
}

// ---------------------------------------------------------------------------
// Kernel 5: fused dst-accumulate + lin2. Warp per dst node, lane = channel u.
// se for up to 32 edges loaded in ONE coalesced load, distributed via shfl
// (no per-edge pointer chase). y/av/h software-pipelined depth-1 so every
// iteration's loads issue a full iteration early. Atomic-free.
// ---------------------------------------------------------------------------
__global__ void __launch_bounds__(256) dst_fused_kernel(
                              const float* __restrict__ ea,
                              const float* __restrict__ fw2,
                              const float* __restrict__ W2s,
                              const float* __restrict__ W2v,
                              float* __restrict__ out) {
    __shared__ float2 sW2[2048];   // [u][w] -> {W2s, W2v}, u in [0,64)
    __shared__ float4 sMid[8][64];

    const int tid = threadIdx.x;
    for (int i = tid; i < 2048; i += 256) sW2[i] = make_float2(W2s[i], W2v[i]);
    __syncthreads();

    const int warp = tid >> 5, lane = tid & 31;
    const int nwarps = gridDim.x * 8;
    const int u = lane;
    const float is8 = 0.3535533905932738f;
    const float IS3 = 0.5773502691896258f;
    const float cc  = 0.25f * 0.125f;        // 1/sqrt(16) * 1/sqrt(64)
    const float4* ea4 = (const float4*)ea;
    const float4* h4  = (const float4*)g_h;

    float w2r[32];                            // [j][c], c = {w00,w01,w10,w11}
#pragma unroll
    for (int j = 0; j < 8; j++)
#pragma unroll
        for (int c = 0; c < 4; c++)
            w2r[j * 4 + c] = __ldg(fw2 + j * 128 + c * 32 + u) * is8;

    for (int n = blockIdx.x * 8 + warp; n < NN; n += nwarps) {
        const int start = g_start[n];
        const int cnt   = g_count[n];

        float As = 0.f, Av0 = 0.f, Av1 = 0.f, Av2 = 0.f;
        float Bs = 0.f, Bv0 = 0.f, Bv1 = 0.f, Bv2 = 0.f;

        for (int base = 0; base < cnt; base += 32) {
            const int m = min(32, cnt - base);
            // one coalesced load covers up to 32 edges' {src, eid}
            int2 sev = make_int2(0, 0);
            if (lane < m) sev = __ldg(&g_se[start + base + lane]);

            // pipeline prologue: t = 0
            int src = __shfl_sync(0xffffffffu, sev.x, 0);
            int e   = __shfl_sync(0xffffffffu, sev.y, 0);
            float4 y  = __ldg(&g_y[src * 32 + u]);
            float4 av = __ldg(ea4 + e);
            float4 h0 = __ldg(h4 + (size_t)e * 2);
            float4 h1 = __ldg(h4 + (size_t)e * 2 + 1);

            for (int t = 0; t < m; t++) {
                const float4 yc = y, avc = av, h0c = h0, h1c = h1;
                if (t + 1 < m) {   // prefetch next edge (warp-uniform branch)
                    src = __shfl_sync(0xffffffffu, sev.x, t + 1);
                    e   = __shfl_sync(0xffffffffu, sev.y, t + 1);
                    y   = __ldg(&g_y[src * 32 + u]);
                    av  = __ldg(ea4 + e);
                    h0  = __ldg(h4 + (size_t)e * 2);
                    h1  = __ldg(h4 + (size_t)e * 2 + 1);
                }

                // MLP layer 2 (register-resident weights, is8 pre-folded)
                float w00, w01, w10, w11;
                w00 = h0c.x * w2r[0];
                w01 = h0c.x * w2r[1];
                w10 = h0c.x * w2r[2];
                w11 = h0c.x * w2r[3];
                w00 = fmaf(h0c.y, w2r[4],  w00); w01 = fmaf(h0c.y, w2r[5],  w01);
                w10 = fmaf(h0c.y, w2r[6],  w10); w11 = fmaf(h0c.y, w2r[7],  w11);
                w00 = fmaf(h0c.z, w2r[8],  w00); w01 = fmaf(h0c.z, w2r[9],  w01);
                w10 = fmaf(h0c.z, w2r[10], w10); w11 = fmaf(h0c.z, w2r[11], w11);
                w00 = fmaf(h0c.w, w2r[12], w00); w01 = fmaf(h0c.w, w2r[13], w01);
                w10 = fmaf(h0c.w, w2r[14], w10); w11 = fmaf(h0c.w, w2r[15], w11);
                w00 = fmaf(h1c.x, w2r[16], w00); w01 = fmaf(h1c.x, w2r[17], w01);
                w10 = fmaf(h1c.x, w2r[18], w10); w11 = fmaf(h1c.x, w2r[19], w11);
                w00 = fmaf(h1c.y, w2r[20], w00); w01 = fmaf(h1c.y, w2r[21], w01);
                w10 = fmaf(h1c.y, w2r[22], w10); w11 = fmaf(h1c.y, w2r[23], w11);
                w00 = fmaf(h1c.z, w2r[24], w00); w01 = fmaf(h1c.z, w2r[25], w01);
                w10 = fmaf(h1c.z, w2r[26], w10); w11 = fmaf(h1c.z, w2r[27], w11);
                w00 = fmaf(h1c.w, w2r[28], w00); w01 = fmaf(h1c.w, w2r[29], w01);
                w10 = fmaf(h1c.w, w2r[30], w10); w11 = fmaf(h1c.w, w2r[31], w11);

                const float es    = yc.x;
                const float dotv  = fmaf(yc.y, avc.y, fmaf(yc.z, avc.z, yc.w * avc.w));
                const float wes   = w01 * es;
                const float w10a0 = w10 * avc.x;

                As  += w00 * es * avc.x;
                Bs  += w11 * dotv * IS3;
                Av0 = fmaf(wes, avc.y, Av0);
                Av1 = fmaf(wes, avc.z, Av1);
                Av2 = fmaf(wes, avc.w, Av2);
                Bv0 = fmaf(w10a0, yc.y, Bv0);
                Bv1 = fmaf(w10a0, yc.z, Bv1);
                Bv2 = fmaf(w10a0, yc.w, Bv2);
            }
        }

        // stage mid into shared, then lin2 (cross-channel mix)
        sMid[warp][u]      = make_float4(As, Av0, Av1, Av2);
        sMid[warp][32 + u] = make_float4(Bs, Bv0, Bv1, Bv2);
        __syncwarp();

        const int w = lane;
        float os = 0.f, ov0 = 0.f, ov1 = 0.f, ov2 = 0.f;
#pragma unroll 16
        for (int uu = 0; uu < 64; uu++) {
            float4 mm = sMid[warp][uu];
            float2 ab = sW2[uu * 32 + w];
            os  = fmaf(mm.x, ab.x, os);
            ov0 = fmaf(mm.y, ab.y, ov0);
            ov1 = fmaf(mm.z, ab.y, ov1);
            ov2 = fmaf(mm.w, ab.y, ov2);
        }

        float* orow = out + (size_t)n * 128;
        orow[w]              += os  * cc;
        orow[32 + w * 3 + 0] += ov0 * cc;
        orow[32 + w * 3 + 1] += ov1 * cc;
        orow[32 + w * 3 + 2] += ov2 * cc;
        __syncwarp();
    }
}

// ---------------------------------------------------------------------------
extern "C" void kernel_launch(void* const* d_in, const int* in_sizes, int n_in,
                              void* d_out, int out_size) {
    const float* nf    = (const float*)d_in[0];   // node_features (N, 128)
    const float* nattr = (const float*)d_in[1];   // node_attr (N, 4)
    const float* eb    = (const float*)d_in[2];   // edge_embedding (E, 8)
    const float* ea    = (const float*)d_in[3];   // edge_attr (E, 4)
    const int*   ei    = (const int*)d_in[4];     // edge_index (2, E)
    const float* W1s   = (const float*)d_in[5];
    const float* W1v   = (const float*)d_in[6];
    const float* fw1   = (const float*)d_in[7];
    const float* fw2   = (const float*)d_in[8];
    const float* W2s   = (const float*)d_in[9];
    const float* W2v   = (const float*)d_in[10];
    const float* Wscs  = (const float*)d_in[11];
    const float* Wscv  = (const float*)d_in[12];
    float* out = (float*)d_out;

    node_prep_kernel<<<1184, 256>>>(nf, nattr, W1s, W1v, Wscs, Wscv, out);
    h_pass_kernel<<<1184, 256>>>(eb, ei, fw1);
    scan1_kernel<<<SCAN_BLOCKS, 1024>>>();
    scan2_kernel<<<1, 64>>>();
    scan3_kernel<<<SCAN_BLOCKS, 1024>>>();
    scatter_kernel<<<1184, 256>>>(ei);
    dst_fused_kernel<<<1184, 256>>>(ea, fw2, W2s, W2v, out);
}